// round 3
// baseline (speedup 1.0000x reference)
#include <cuda_runtime.h>
#include <cuda_bf16.h>
#include <math.h>

// Problem constants
#define B     16384
#define IN    64
#define HID   128
#define E     64
#define NMAP  1000
#define TILE_M 64
#define MAX_TILES (B / TILE_M + E)   // 320 upper bound on sum ceil(cnt_e/TILE_M)

// Scratch (device globals: no allocation allowed in kernel_launch)
__device__ int g_e[B];
__device__ int g_counts[E];
__device__ int g_offsets[E];
__device__ int g_cursor[E];
__device__ int g_bucket[B];
__device__ int g_tileExpert[MAX_TILES];
__device__ int g_tileIdx[MAX_TILES];
__device__ int g_numTiles;
__device__ int g_stride;   // 1 if inputs are int32, 2 if int64 (little-endian low word)

// ---------------------------------------------------------------------------
// K0: zero histogram + detect integer width of `c` (and by extension `num`).
// If c is int64 with values in [0,64), every odd 32-bit word of the first 64
// is zero. For int32 random data that is (1/64)^32 ~ impossible.
__global__ void zero_detect_kernel(const int* __restrict__ c32) {
    int t = threadIdx.x;
    if (t < E) g_counts[t] = 0;
    if (t == 0) {
        int is64 = 1;
        for (int j = 1; j < 64; j += 2)
            if (c32[j] != 0) { is64 = 0; break; }
        g_stride = is64 ? 2 : 1;
    }
}

// K1: expert id per sample + histogram (smem-local, then merge)
__global__ void hist_kernel(const int* __restrict__ num32,
                            const int* __restrict__ c32) {
    __shared__ int hs[E];
    if (threadIdx.x < E) hs[threadIdx.x] = 0;
    __syncthreads();
    int stride = g_stride;
    int i = blockIdx.x * blockDim.x + threadIdx.x;
    if (i < B) {
        int n = num32[(size_t)i * stride];
        n = n < 0 ? 0 : (n >= NMAP ? NMAP - 1 : n);        // safety clamp
        int e = c32[(size_t)n * stride];
        e = e < 0 ? 0 : (e >= E ? E - 1 : e);              // safety clamp
        g_e[i] = e;
        atomicAdd(&hs[e], 1);
    }
    __syncthreads();
    if (threadIdx.x < E) {
        int v = hs[threadIdx.x];
        if (v) atomicAdd(&g_counts[threadIdx.x], v);
    }
}

// K2: serial scan (E=64 — trivial) + tile map construction
__global__ void scan_kernel() {
    if (threadIdx.x == 0) {
        int off = 0, t = 0;
        for (int e = 0; e < E; e++) {
            g_offsets[e] = off;
            g_cursor[e]  = off;
            int cnt = g_counts[e];
            int nt = (cnt + TILE_M - 1) / TILE_M;
            for (int j = 0; j < nt; j++) {
                g_tileExpert[t] = e;
                g_tileIdx[t]    = j;
                t++;
            }
            off += cnt;
        }
        g_numTiles = t;
    }
}

// K3: scatter sample indices into per-expert buckets
__global__ void scatter_kernel() {
    int i = blockIdx.x * blockDim.x + threadIdx.x;
    if (i < B) {
        int e = g_e[i];
        int p = atomicAdd(&g_cursor[e], 1);
        g_bucket[p] = i;
    }
}

// ---------------------------------------------------------------------------
// K4: per-tile fused MLP.
// CTA = one (expert, tile of 64 samples). 256 threads.
// Thread (tx, ty): tx = tid & 15 -> 8 hidden units [tx*8, tx*8+8)
//                  ty = tid >> 4 -> 4 samples      [ty*4, ty*4+4)
// SMEM: sX[k][m] transposed X tile (64x64 = 16KB), sW[k][h] W1 tile (64x128 = 32KB)
__global__ __launch_bounds__(256) void mlp_kernel(
    const float* __restrict__ x,
    const float* __restrict__ W1,
    const float* __restrict__ b1,
    const float* __restrict__ W2,
    const float* __restrict__ b2,
    float* __restrict__ out)
{
    __shared__ float sX[IN * TILE_M];    // sX[k*64 + m]
    __shared__ float sW[IN * HID];       // sW[k*128 + h]

    int tile = blockIdx.x;
    if (tile >= g_numTiles) return;

    int e    = g_tileExpert[tile];
    int ti   = g_tileIdx[tile];
    int cnt  = g_counts[e];
    int base = g_offsets[e] + ti * TILE_M;
    int mvalid = cnt - ti * TILE_M;
    if (mvalid > TILE_M) mvalid = TILE_M;

    // ---- Load W1[e] (8192 floats) coalesced: 256 thr x 8 float4
    {
        const float4* Wg  = (const float4*)(W1 + (size_t)e * IN * HID);
        float4*       Ws4 = (float4*)sW;
        #pragma unroll
        for (int i = threadIdx.x; i < (IN * HID) / 4; i += 256)
            Ws4[i] = Wg[i];
    }

    // ---- Load X tile transposed: thread t handles row m = t/4, k-chunk (t%4)*16
    {
        int m  = threadIdx.x >> 2;
        int kq = (threadIdx.x & 3) * 16;
        int mc = m < mvalid ? m : (mvalid - 1);      // clamp (dup row; outputs guarded)
        int gidx = g_bucket[base + mc];
        const float4* xr = (const float4*)(x + (size_t)gidx * IN + kq);
        #pragma unroll
        for (int q = 0; q < 4; q++) {
            float4 v = xr[q];
            int k0 = kq + q * 4;
            sX[(k0 + 0) * TILE_M + m] = v.x;
            sX[(k0 + 1) * TILE_M + m] = v.y;
            sX[(k0 + 2) * TILE_M + m] = v.z;
            sX[(k0 + 3) * TILE_M + m] = v.w;
        }
    }
    __syncthreads();

    int tx = threadIdx.x & 15;   // hid group
    int ty = threadIdx.x >> 4;   // sample group

    float acc[4][8];
    #pragma unroll
    for (int mm = 0; mm < 4; mm++)
        #pragma unroll
        for (int j = 0; j < 8; j++)
            acc[mm][j] = 0.0f;

    // ---- Mainloop: K = 64, 4x8 register tile per thread
    #pragma unroll 4
    for (int k = 0; k < IN; k++) {
        float4 a4  = *(const float4*)&sX[k * TILE_M + ty * 4];
        float4 b0  = *(const float4*)&sW[k * HID + tx * 8];
        float4 b1v = *(const float4*)&sW[k * HID + tx * 8 + 4];
        float a[4] = {a4.x, a4.y, a4.z, a4.w};
        float bb[8] = {b0.x, b0.y, b0.z, b0.w, b1v.x, b1v.y, b1v.z, b1v.w};
        #pragma unroll
        for (int mm = 0; mm < 4; mm++)
            #pragma unroll
            for (int j = 0; j < 8; j++)
                acc[mm][j] = fmaf(a[mm], bb[j], acc[mm][j]);
    }

    // ---- Epilogue: +b1, relu, dot with w2 (partial), reduce across 16 tx groups
    float b1r[8], w2r[8];
    {
        const float* b1e = b1 + (size_t)e * HID + tx * 8;
        const float* w2e = W2 + (size_t)e * HID + tx * 8;   // OUT=1
        #pragma unroll
        for (int j = 0; j < 8; j++) { b1r[j] = b1e[j]; w2r[j] = w2e[j]; }
    }

    __syncthreads();   // mainloop reads of sX done; reuse as reduction buffer

    #pragma unroll
    for (int mm = 0; mm < 4; mm++) {
        float p = 0.0f;
        #pragma unroll
        for (int j = 0; j < 8; j++) {
            float h = acc[mm][j] + b1r[j];
            h = h > 0.0f ? h : 0.0f;
            p = fmaf(h, w2r[j], p);
        }
        sX[(ty * 4 + mm) * 16 + tx] = p;
    }
    __syncthreads();

    if (threadIdx.x < TILE_M) {
        int m = threadIdx.x;
        if (m < mvalid) {
            float s = 0.0f;
            #pragma unroll
            for (int t = 0; t < 16; t++) s += sX[m * 16 + t];
            float y = s + b2[e];
            int gidx = g_bucket[base + m];
            out[gidx] = 1.0f / (1.0f + expf(-y));
        }
    }
}

// ---------------------------------------------------------------------------
extern "C" void kernel_launch(void* const* d_in, const int* in_sizes, int n_in,
                              void* d_out, int out_size) {
    const float* x     = (const float*)d_in[0];
    const int*   num32 = (const int*)d_in[1];
    const int*   c32   = (const int*)d_in[2];
    const float* W1    = (const float*)d_in[3];
    const float* b1    = (const float*)d_in[4];
    const float* W2    = (const float*)d_in[5];
    const float* b2    = (const float*)d_in[6];
    float*       out   = (float*)d_out;

    zero_detect_kernel<<<1, 64>>>(c32);
    hist_kernel<<<B / 256, 256>>>(num32, c32);
    scan_kernel<<<1, 32>>>();
    scatter_kernel<<<B / 256, 256>>>();
    mlp_kernel<<<MAX_TILES, 256>>>(x, W1, b1, W2, b2, out);
}

// round 4
// speedup vs baseline: 1.1988x; 1.1988x over previous
#include <cuda_runtime.h>
#include <math.h>

// Problem constants
#define B      16384
#define IN     64
#define HID    128
#define E      64
#define NMAP   1000
#define TILE_M 128
#define NBLK   64                      // binning blocks (B/256)
#define MAX_TILES (B / TILE_M + E)     // 192

// Scratch (device globals; no allocation allowed)
__device__ int g_e[B];
__device__ int g_hist[NBLK * E];       // per-block histogram rows
__device__ int g_blockpref[NBLK * E];  // prefix over blocks, per expert
__device__ int g_expOff[E];
__device__ int g_counts[E];
__device__ int g_bucket[B];
__device__ int g_tileExpert[MAX_TILES];
__device__ int g_tileIdx[MAX_TILES];
__device__ int g_numTiles;

// ---------------------------------------------------------------------------
// K1: expert id per sample + per-block histogram (NO global atomics).
// dtype width of num/c detected per-block (int64 -> odd 32-bit words all zero).
__global__ void hist_kernel(const int* __restrict__ num32,
                            const int* __restrict__ c32) {
    __shared__ int hs[E];
    __shared__ int s_stride;
    int t = threadIdx.x, b = blockIdx.x;
    if (t == 0) {
        int is64 = 1;
        for (int j = 1; j < 64; j += 2)
            if (c32[j] != 0) { is64 = 0; break; }
        s_stride = is64 ? 2 : 1;
    }
    if (t < E) hs[t] = 0;
    __syncthreads();
    int stride = s_stride;
    int i = b * 256 + t;
    int n = num32[(size_t)i * stride];
    n = n < 0 ? 0 : (n >= NMAP ? NMAP - 1 : n);
    int e = c32[(size_t)n * stride];
    e = e < 0 ? 0 : (e >= E ? E - 1 : e);
    g_e[i] = e;
    atomicAdd(&hs[e], 1);
    __syncthreads();
    if (t < E) g_hist[b * E + t] = hs[t];
}

// ---------------------------------------------------------------------------
// K2: parallel scan. 64 threads: thread e owns expert column e.
__global__ void scan_kernel() {
    __shared__ int s_cnt[E];
    __shared__ int s_nt[E];
    int e = threadIdx.x;           // 0..63
    int acc = 0;
    #pragma unroll 4
    for (int b = 0; b < NBLK; b++) {
        g_blockpref[b * E + e] = acc;
        acc += g_hist[b * E + e];
    }
    g_counts[e] = acc;
    s_cnt[e] = acc;
    s_nt[e]  = (acc + TILE_M - 1) / TILE_M;
    __syncthreads();
    if (e == 0) {
        int run = 0;
        for (int j = 0; j < E; j++) { int v = s_cnt[j]; s_cnt[j] = run; run += v; }
        run = 0;
        for (int j = 0; j < E; j++) { int v = s_nt[j];  s_nt[j]  = run; run += v; }
        g_numTiles = run;
    }
    __syncthreads();
    g_expOff[e] = s_cnt[e];
    int t0 = s_nt[e];
    int nt = (g_counts[e] + TILE_M - 1) / TILE_M;
    for (int j = 0; j < nt; j++) {
        g_tileExpert[t0 + j] = e;
        g_tileIdx[t0 + j]    = j;
    }
}

// ---------------------------------------------------------------------------
// K3: scatter via counting-sort placement (smem atomics only).
__global__ void scatter_kernel() {
    __shared__ int loc[E];
    __shared__ int basev[E];
    int t = threadIdx.x, b = blockIdx.x;
    if (t < E) {
        loc[t]   = 0;
        basev[t] = g_expOff[t] + g_blockpref[b * E + t];
    }
    __syncthreads();
    int i = b * 256 + t;
    int e = g_e[i];
    int r = atomicAdd(&loc[e], 1);
    g_bucket[basev[e] + r] = i;
}

// ---------------------------------------------------------------------------
// K4: per-tile fused MLP. CTA = (expert, 128-sample tile), 256 threads.
// tx = tid&15 -> 8 hidden units; ty = tid>>4 -> 8 samples. 8x8 register tile.
// Dynamic SMEM 64KB: sW[k*128+h] (32KB) + sX[k*128+m] (32KB).
__global__ __launch_bounds__(256) void mlp_kernel(
    const float* __restrict__ x,
    const float* __restrict__ W1,
    const float* __restrict__ b1,
    const float* __restrict__ W2,
    const float* __restrict__ b2,
    float* __restrict__ out)
{
    extern __shared__ float smem[];
    float* sW = smem;                // IN*HID  = 8192 floats
    float* sX = smem + IN * HID;     // IN*TILE_M = 8192 floats

    int tile = blockIdx.x;
    if (tile >= g_numTiles) return;

    int e    = g_tileExpert[tile];
    int ti   = g_tileIdx[tile];
    int cnt  = g_counts[e];
    int base = g_expOff[e] + ti * TILE_M;
    int mvalid = cnt - ti * TILE_M;
    if (mvalid > TILE_M) mvalid = TILE_M;

    // ---- Load W1[e]: 2048 float4 across 256 threads
    {
        const float4* Wg  = (const float4*)(W1 + (size_t)e * IN * HID);
        float4*       Ws4 = (float4*)sW;
        #pragma unroll
        for (int i = threadIdx.x; i < (IN * HID) / 4; i += 256)
            Ws4[i] = Wg[i];
    }

    // ---- Load X tile transposed: 2 threads per row, 32-float half-rows
    {
        int m  = threadIdx.x >> 1;
        int kq = (threadIdx.x & 1) * 32;
        int mc = m < mvalid ? m : (mvalid - 1);
        int gidx = g_bucket[base + mc];
        const float4* xr = (const float4*)(x + (size_t)gidx * IN + kq);
        #pragma unroll
        for (int q = 0; q < 8; q++) {
            float4 v = xr[q];
            int k0 = kq + q * 4;
            sX[(k0 + 0) * TILE_M + m] = v.x;
            sX[(k0 + 1) * TILE_M + m] = v.y;
            sX[(k0 + 2) * TILE_M + m] = v.z;
            sX[(k0 + 3) * TILE_M + m] = v.w;
        }
    }
    __syncthreads();

    int tx = threadIdx.x & 15;   // hid group (8 units)
    int ty = threadIdx.x >> 4;   // sample group (8 samples)

    float acc[8][8];
    #pragma unroll
    for (int mm = 0; mm < 8; mm++)
        #pragma unroll
        for (int j = 0; j < 8; j++)
            acc[mm][j] = 0.0f;

    // ---- Mainloop: K=64, 8x8 register tile (64 FMA per k per thread)
    #pragma unroll 2
    for (int k = 0; k < IN; k++) {
        float4 a0 = *(const float4*)&sX[k * TILE_M + ty * 8];
        float4 a1 = *(const float4*)&sX[k * TILE_M + ty * 8 + 4];
        float4 w0 = *(const float4*)&sW[k * HID + tx * 8];
        float4 w1 = *(const float4*)&sW[k * HID + tx * 8 + 4];
        float a[8]  = {a0.x, a0.y, a0.z, a0.w, a1.x, a1.y, a1.z, a1.w};
        float bb[8] = {w0.x, w0.y, w0.z, w0.w, w1.x, w1.y, w1.z, w1.w};
        #pragma unroll
        for (int mm = 0; mm < 8; mm++)
            #pragma unroll
            for (int j = 0; j < 8; j++)
                acc[mm][j] = fmaf(a[mm], bb[j], acc[mm][j]);
    }

    // ---- Epilogue: +b1, relu, partial dot with w2, reduce over 16 tx groups
    float b1r[8], w2r[8];
    {
        const float* b1e = b1 + (size_t)e * HID + tx * 8;
        const float* w2e = W2 + (size_t)e * HID + tx * 8;   // OUT=1
        #pragma unroll
        for (int j = 0; j < 8; j++) { b1r[j] = b1e[j]; w2r[j] = w2e[j]; }
    }

    __syncthreads();   // done reading sX/sW; reuse sX as reduction buffer
    // reduction buffer: sX[row*17 + tx], rows 0..127 (padded stride 17)

    #pragma unroll
    for (int mm = 0; mm < 8; mm++) {
        float p = 0.0f;
        #pragma unroll
        for (int j = 0; j < 8; j++) {
            float h = acc[mm][j] + b1r[j];
            h = h > 0.0f ? h : 0.0f;
            p = fmaf(h, w2r[j], p);
        }
        sX[(ty * 8 + mm) * 17 + tx] = p;
    }
    __syncthreads();

    if (threadIdx.x < TILE_M) {
        int m = threadIdx.x;
        if (m < mvalid) {
            float s = 0.0f;
            #pragma unroll
            for (int t = 0; t < 16; t++) s += sX[m * 17 + t];
            float y = s + b2[e];
            int gidx = g_bucket[base + m];
            out[gidx] = 1.0f / (1.0f + expf(-y));
        }
    }
}

// ---------------------------------------------------------------------------
extern "C" void kernel_launch(void* const* d_in, const int* in_sizes, int n_in,
                              void* d_out, int out_size) {
    const float* x     = (const float*)d_in[0];
    const int*   num32 = (const int*)d_in[1];
    const int*   c32   = (const int*)d_in[2];
    const float* W1    = (const float*)d_in[3];
    const float* b1    = (const float*)d_in[4];
    const float* W2    = (const float*)d_in[5];
    const float* b2    = (const float*)d_in[6];
    float*       out   = (float*)d_out;

    static bool attr_set = false;
    if (!attr_set) {
        cudaFuncSetAttribute(mlp_kernel,
                             cudaFuncAttributeMaxDynamicSharedMemorySize,
                             64 * 1024);
        attr_set = true;
    }

    hist_kernel<<<NBLK, 256>>>(num32, c32);
    scan_kernel<<<1, 64>>>();
    scatter_kernel<<<NBLK, 256>>>();
    mlp_kernel<<<MAX_TILES, 256, 64 * 1024>>>(x, W1, b1, W2, b2, out);
}